// round 1
// baseline (speedup 1.0000x reference)
#include <cuda_runtime.h>
#include <math.h>

#define HDIM 1024
#define TSTEPS 256
#define VOCAB 50257

#define NB1 128          // persistent blocks for the recurrence (< 148 SMs -> co-resident)
#define ROWS_PER_BLK (HDIM / NB1)   // 8 rows per block, one warp per row

// -------- device scratch (no allocations allowed) --------
__device__ __align__(16) float g_X[TSTEPS * HDIM];   // Wxh[:, c_t] + bh
__device__ __align__(16) float g_H[TSTEPS * HDIM];   // all hidden states h_t
__device__ unsigned g_bar;                           // grid barrier counter

// ---------------- init: reset barrier every launch (determinism across graph replays)
__global__ void init_kernel() {
    if (threadIdx.x == 0) g_bar = 0u;
}

// ---------------- gather: g_X[t][h] = Wxh[h][c_t] + bh[h]
__global__ void gather_x_kernel(const int* __restrict__ chars,
                                const float* __restrict__ Wxh,
                                const float* __restrict__ bh) {
    int t = blockIdx.x;
    int h = blockIdx.y * blockDim.x + threadIdx.x;
    int c = chars[t];
    g_X[t * HDIM + h] = Wxh[(size_t)h * VOCAB + c] + bh[h];
}

// ---------------- phase 1: sequential recurrence, persistent kernel, grid barrier.
// Each warp owns one row of Whh, held fully in registers (32 floats/lane).
__global__ void __launch_bounds__(256, 1) rnn_steps_kernel(const float* __restrict__ Whh,
                                                           const float* __restrict__ h0) {
    __shared__ float sh[HDIM];
    const int warp = threadIdx.x >> 5;
    const int lane = threadIdx.x & 31;
    const int row  = blockIdx.x * ROWS_PER_BLK + warp;

    // Load this warp's Whh row into registers: 8 float4 per lane.
    float4 w[8];
    const float4* wrow = reinterpret_cast<const float4*>(Whh + (size_t)row * HDIM);
#pragma unroll
    for (int j = 0; j < 8; ++j) w[j] = wrow[j * 32 + lane];

    for (int t = 0; t < TSTEPS; ++t) {
        // stage h_{t-1} into shared memory (1 float4 per thread)
        const float* hprev = (t == 0) ? h0 : (g_H + (size_t)(t - 1) * HDIM);
        reinterpret_cast<float4*>(sh)[threadIdx.x] =
            reinterpret_cast<const float4*>(hprev)[threadIdx.x];
        __syncthreads();

        float acc = 0.f;
#pragma unroll
        for (int j = 0; j < 8; ++j) {
            float4 hv = reinterpret_cast<const float4*>(sh)[j * 32 + lane];
            acc += w[j].x * hv.x + w[j].y * hv.y + w[j].z * hv.z + w[j].w * hv.w;
        }
#pragma unroll
        for (int o = 16; o > 0; o >>= 1)
            acc += __shfl_down_sync(0xffffffffu, acc, o);

        if (lane == 0)
            g_H[(size_t)t * HDIM + row] = tanhf(acc + g_X[(size_t)t * HDIM + row]);

        // ---- grid-wide barrier (release: fence + arrive; acquire: poll + fence)
        __threadfence();
        __syncthreads();
        if (threadIdx.x == 0) {
            atomicAdd(&g_bar, 1u);
            unsigned target = (unsigned)NB1 * (unsigned)(t + 1);
            while (*((volatile unsigned*)&g_bar) < target) { }
        }
        __syncthreads();
        __threadfence();
    }
}

// ---------------- phase 2: logits[t][v] = sum_k Why[v][k] * H[t][k] + by[v]
// Classic fp32 smem-tiled GEMM: BM=128 (v), BN=128 (t), BK=16, 256 threads, 8x8/thread.
#define BM 128
#define BN 128
#define BK 16
#define TM 8
#define TN 8

__global__ void __launch_bounds__(256) gemm_logits_kernel(const float* __restrict__ Why,
                                                          const float* __restrict__ by,
                                                          float* __restrict__ out) {
    __shared__ float As[BK][BM];   // Why tile, transposed
    __shared__ float Bs[BK][BN];   // H tile, transposed

    const int tid = threadIdx.x;
    const int tx = tid & 15;       // t direction
    const int ty = tid >> 4;       // v direction
    const int m0 = blockIdx.x * BM;   // vocab offset
    const int n0 = blockIdx.y * BN;   // time offset

    float acc[TM][TN] = {};

    for (int k0 = 0; k0 < HDIM; k0 += BK) {
        // load A tile (Why): 128x16 floats, transposed into As[k][m]
#pragma unroll
        for (int q = 0; q < 2; ++q) {
            int ar = (tid >> 2) + q * 64;      // 0..127
            int ac = (tid & 3) * 4;            // 0,4,8,12
            int gm = m0 + ar;
            float4 v4 = make_float4(0.f, 0.f, 0.f, 0.f);
            if (gm < VOCAB)
                v4 = *reinterpret_cast<const float4*>(Why + (size_t)gm * HDIM + k0 + ac);
            As[ac + 0][ar] = v4.x; As[ac + 1][ar] = v4.y;
            As[ac + 2][ar] = v4.z; As[ac + 3][ar] = v4.w;
        }
        // load B tile (g_H): rows n0..n0+127 always valid (T=256)
#pragma unroll
        for (int q = 0; q < 2; ++q) {
            int br = (tid >> 2) + q * 64;
            int bc = (tid & 3) * 4;
            float4 v4 = *reinterpret_cast<const float4*>(g_H + (size_t)(n0 + br) * HDIM + k0 + bc);
            Bs[bc + 0][br] = v4.x; Bs[bc + 1][br] = v4.y;
            Bs[bc + 2][br] = v4.z; Bs[bc + 3][br] = v4.w;
        }
        __syncthreads();

#pragma unroll
        for (int k = 0; k < BK; ++k) {
            float a[TM], b[TN];
#pragma unroll
            for (int i = 0; i < TM; ++i) a[i] = As[k][ty * TM + i];
#pragma unroll
            for (int j = 0; j < TN; ++j) b[j] = Bs[k][tx * TN + j];
#pragma unroll
            for (int i = 0; i < TM; ++i)
#pragma unroll
                for (int j = 0; j < TN; ++j)
                    acc[i][j] += a[i] * b[j];
        }
        __syncthreads();
    }

    // epilogue: out[t][v] = acc + by[v]
    float bias[TM];
#pragma unroll
    for (int i = 0; i < TM; ++i) {
        int v = m0 + ty * TM + i;
        bias[i] = (v < VOCAB) ? by[v] : 0.f;
    }
#pragma unroll
    for (int j = 0; j < TN; ++j) {
        int t = n0 + tx * TN + j;
#pragma unroll
        for (int i = 0; i < TM; ++i) {
            int v = m0 + ty * TM + i;
            if (v < VOCAB)
                out[(size_t)t * VOCAB + v] = acc[i][j] + bias[i];
        }
    }
}

// ---------------- phase 3: in-place stable softmax over each row of 50257
__global__ void __launch_bounds__(1024) softmax_rows_kernel(float* __restrict__ out) {
    __shared__ float red[1024];
    const int t = blockIdx.x;
    float* row = out + (size_t)t * VOCAB;
    const int tid = threadIdx.x;

    // pass 1: max
    float m = -1e30f;
    for (int i = tid; i < VOCAB; i += 1024) m = fmaxf(m, row[i]);
    red[tid] = m; __syncthreads();
    for (int s = 512; s > 0; s >>= 1) {
        if (tid < s) red[tid] = fmaxf(red[tid], red[tid + s]);
        __syncthreads();
    }
    m = red[0];
    __syncthreads();

    // pass 2: sum of exp
    float sum = 0.f;
    for (int i = tid; i < VOCAB; i += 1024) sum += expf(row[i] - m);
    red[tid] = sum; __syncthreads();
    for (int s = 512; s > 0; s >>= 1) {
        if (tid < s) red[tid] += red[tid + s];
        __syncthreads();
    }
    float inv = 1.0f / red[0];
    __syncthreads();

    // pass 3: write probs
    for (int i = tid; i < VOCAB; i += 1024) row[i] = expf(row[i] - m) * inv;
}

// ---------------- launch ----------------
extern "C" void kernel_launch(void* const* d_in, const int* in_sizes, int n_in,
                              void* d_out, int out_size) {
    const int*   chars = (const int*)  d_in[0];   // (T,)
    const float* Wxh   = (const float*)d_in[1];   // (H, V)
    const float* Whh   = (const float*)d_in[2];   // (H, H)
    const float* Why   = (const float*)d_in[3];   // (V, H)
    const float* bh    = (const float*)d_in[4];   // (H,)
    const float* by    = (const float*)d_in[5];   // (V,)
    const float* h0    = (const float*)d_in[6];   // (H,)
    float* out = (float*)d_out;                   // (T, V)

    init_kernel<<<1, 32>>>();
    gather_x_kernel<<<dim3(TSTEPS, HDIM / 256), 256>>>(chars, Wxh, bh);
    rnn_steps_kernel<<<NB1, 256>>>(Whh, h0);
    gemm_logits_kernel<<<dim3((VOCAB + BM - 1) / BM, TSTEPS / BN), 256>>>(Why, by, out);
    softmax_rows_kernel<<<TSTEPS, 1024>>>(out);
}